// round 1
// baseline (speedup 1.0000x reference)
#include <cuda_runtime.h>
#include <math.h>

// Problem constants
#define N      256
#define BATCH  32
#define PM     4
#define NS     8
#define NIMG   (BATCH*PM)     // 128 images (batch x probe-mode)
#define INV256 (1.0f/256.0f)
#define ROWP   272            // 256 + skew padding

// Scratch: psi[img][y][x], complex64. 128*256*256*8B = 64MB.
__device__ float2 g_psi[NIMG * N * N];

__device__ __forceinline__ float2 cmulf(float2 a, float2 b){
    return make_float2(a.x*b.x - a.y*b.y, a.x*b.y + a.y*b.x);
}
__device__ __forceinline__ int SK(int i){ return i + (i >> 4); }  // bank-conflict skew

// ---------------------------------------------------------------------------
// Radix-4 Stockham FFT, length 256, 64 cooperating lanes per FFT.
// Data starts in A (skewed layout), ends in A (4 stages, even # of swaps).
// Block-wide __syncthreads inside; all threads of the block must call.
// Forward: exp(-2pi i nk/N), no scale. Inverse: conj twiddles, no scale.
// ---------------------------------------------------------------------------
template<bool INV>
__device__ void fft256(float2* A, float2* B, const float2* tw, int lane){
    float2* src = A; float2* dst = B;
    int s = 1;
    #pragma unroll
    for (int st = 0; st < 4; st++){
        __syncthreads();
        int p = lane / s;          // s = 1,4,16,64
        int q = lane - p * s;
        float2 a = src[SK(lane)];
        float2 b = src[SK(lane + 64)];
        float2 c = src[SK(lane + 128)];
        float2 d = src[SK(lane + 192)];
        float2 apc = make_float2(a.x + c.x, a.y + c.y);
        float2 amc = make_float2(a.x - c.x, a.y - c.y);
        float2 bpd = make_float2(b.x + d.x, b.y + d.y);
        float2 bmd = make_float2(b.x - d.x, b.y - d.y);
        float2 t0  = make_float2(apc.x + bpd.x, apc.y + bpd.y);
        float2 t2  = make_float2(apc.x - bpd.x, apc.y - bpd.y);
        float2 t1, t3;
        if (!INV){ // fwd: t1 = amc - i*bmd ; t3 = amc + i*bmd
            t1 = make_float2(amc.x + bmd.y, amc.y - bmd.x);
            t3 = make_float2(amc.x - bmd.y, amc.y + bmd.x);
        } else {   // inv: swap
            t1 = make_float2(amc.x - bmd.y, amc.y + bmd.x);
            t3 = make_float2(amc.x + bmd.y, amc.y - bmd.x);
        }
        int k = p << (2 * st);     // twiddle index scale = 256/n
        float2 w1 = tw[k];
        float2 w2 = tw[2 * k];
        float2 w3 = tw[3 * k];
        if (INV){ w1.y = -w1.y; w2.y = -w2.y; w3.y = -w3.y; }
        int j0 = lane + 3 * s * p; // = q + 4*s*p
        dst[SK(j0)]         = t0;
        dst[SK(j0 + s)]     = cmulf(w1, t1);
        dst[SK(j0 + 2*s)]   = cmulf(w2, t2);
        dst[SK(j0 + 3*s)]   = cmulf(w3, t3);
        float2* tmp = src; src = dst; dst = tmp;
        s <<= 2;
    }
    __syncthreads();
}

__device__ __forceinline__ void fill_tw(float2* tw, int tid){
    if (tid < 256){
        float sv, cv;
        sincospif(-(float)tid * (1.0f / 128.0f), &sv, &cv); // exp(-2pi i k/256)
        tw[tid] = make_float2(cv, sv);
    }
}

// ---------------------------------------------------------------------------
// k_init: psi = (bilinear-translated probe amp/phase -> complex) * obj_c[z=0]
//         followed by forward ROW FFT. Block = (b, y), 4 modes, 256 threads.
// ---------------------------------------------------------------------------
__global__ __launch_bounds__(256) void k_init(
    const float* __restrict__ obj, const float* __restrict__ probe,
    const float* __restrict__ shifts, const int* __restrict__ crop,
    const int* __restrict__ indices)
{
    __shared__ float2 tw[256];
    __shared__ float2 objc[256];
    __shared__ float2 bufA[PM][ROWP];
    __shared__ float2 bufB[PM][ROWP];

    int tid = threadIdx.x;
    int y   = blockIdx.x;
    int b   = blockIdx.y;
    int idx = indices[b];
    int p0  = crop[2*idx], p1 = crop[2*idx + 1];
    float sH = shifts[2*idx], sW = shifts[2*idx + 1];

    fill_tw(tw, tid);

    // object row, slice 0 -> complex
    {
        int off = (((p0 + y) * 1024) + (p1 + tid)) * 2;  // z=0
        float amp = obj[off], ph = obj[off + 1];
        float sv, cv; sincosf(ph, &sv, &cv);
        objc[tid] = make_float2(amp * cv, amp * sv);
    }

    // bilinear constants (fractional part uniform across the image)
    float fy = -sH, fx = -sW;
    float Fy = floorf(fy), Fx = floorf(fx);
    int   ky = (int)Fy,  kx = (int)Fx;
    float wy = fy - Fy,  wx = fx - Fx;
    int r0 = y + ky, r1 = r0 + 1;
    bool vy0 = (r0 >= 0 && r0 < 256), vy1 = (r1 >= 0 && r1 < 256);
    int r0c = min(max(r0, 0), 255), r1c = min(max(r1, 0), 255);

    int f = tid >> 6, lane = tid & 63;
    __syncthreads();  // objc ready

    #pragma unroll
    for (int j = 0; j < 4; j++){
        int x  = lane + 64 * j;
        int c0 = x + kx, c1 = c0 + 1;
        bool vx0 = (c0 >= 0 && c0 < 256), vx1 = (c1 >= 0 && c1 < 256);
        int c0c = min(max(c0, 0), 255), c1c = min(max(c1, 0), 255);
        float w00 = (1.0f - wy) * (1.0f - wx) * ((vy0 && vx0) ? 1.0f : 0.0f);
        float w01 = (1.0f - wy) * wx          * ((vy0 && vx1) ? 1.0f : 0.0f);
        float w10 = wy * (1.0f - wx)          * ((vy1 && vx0) ? 1.0f : 0.0f);
        float w11 = wy * wx                   * ((vy1 && vx1) ? 1.0f : 0.0f);
        const float* P = probe + f * 256 * 256 * 2;
        int o00 = (r0c * 256 + c0c) * 2;
        int o01 = (r0c * 256 + c1c) * 2;
        int o10 = (r1c * 256 + c0c) * 2;
        int o11 = (r1c * 256 + c1c) * 2;
        float amp = w00*P[o00]   + w01*P[o01]   + w10*P[o10]   + w11*P[o11];
        float ph  = w00*P[o00+1] + w01*P[o01+1] + w10*P[o10+1] + w11*P[o11+1];
        float sv, cv; sincosf(ph, &sv, &cv);
        float2 pc = make_float2(amp * cv, amp * sv);
        bufA[f][SK(x)] = cmulf(pc, objc[x]);
    }

    fft256<false>(bufA[f], bufB[f], tw, lane);

    int base = ((b * PM + f) * N + y) * N;
    #pragma unroll
    for (int j = 0; j < 4; j++){
        int x = lane + 64 * j;
        g_psi[base + x] = bufA[f][SK(x)];
    }
}

// ---------------------------------------------------------------------------
// k_col: column FFT -> * (H/256) -> column iFFT. Block = (img, 8 columns),
// 512 threads (8 FFTs x 64 lanes).
// ---------------------------------------------------------------------------
__global__ __launch_bounds__(512) void k_col(
    const float* __restrict__ Hr, const float* __restrict__ Hi)
{
    __shared__ float2 tw[256];
    __shared__ float2 bufA[8][ROWP];
    __shared__ float2 bufB[8][ROWP];

    int tid = threadIdx.x;
    int img = blockIdx.y;
    int x0  = blockIdx.x * 8;
    fill_tw(tw, tid);

    int base = img * (N * N);
    #pragma unroll
    for (int r = 0; r < 4; r++){
        int e = tid + 512 * r;
        int yy = e >> 3, cc = e & 7;
        bufA[cc][SK(yy)] = g_psi[base + yy * N + x0 + cc];
    }

    int f = tid >> 6, lane = tid & 63;
    fft256<false>(bufA[f], bufB[f], tw, lane);

    #pragma unroll
    for (int j = 0; j < 4; j++){
        int yy = lane + 64 * j;
        float hr = Hr[yy * N + x0 + f] * INV256;
        float hi = Hi[yy * N + x0 + f] * INV256;
        bufA[f][SK(yy)] = cmulf(bufA[f][SK(yy)], make_float2(hr, hi));
    }

    fft256<true>(bufA[f], bufB[f], tw, lane);

    #pragma unroll
    for (int r = 0; r < 4; r++){
        int e = tid + 512 * r;
        int yy = e >> 3, cc = e & 7;
        g_psi[base + yy * N + x0 + cc] = bufA[cc][SK(yy)];
    }
}

// ---------------------------------------------------------------------------
// k_row: row iFFT -> * (obj_z/256) -> row FFT. Block = (b, y), 4 modes,
// 256 threads. (Fuses end of one propagation with start of the next.)
// ---------------------------------------------------------------------------
__global__ __launch_bounds__(256) void k_row(
    const float* __restrict__ obj, const int* __restrict__ crop,
    const int* __restrict__ indices, int z)
{
    __shared__ float2 tw[256];
    __shared__ float2 objc[256];
    __shared__ float2 bufA[PM][ROWP];
    __shared__ float2 bufB[PM][ROWP];

    int tid = threadIdx.x;
    int y = blockIdx.x, b = blockIdx.y;
    int idx = indices[b];
    int p0 = crop[2*idx], p1 = crop[2*idx + 1];
    fill_tw(tw, tid);

    {
        int off = ((z * 1024 + p0 + y) * 1024 + (p1 + tid)) * 2;
        float amp = obj[off] * INV256;     // fold ifft row-scale into obj
        float ph  = obj[off + 1];
        float sv, cv; sincosf(ph, &sv, &cv);
        objc[tid] = make_float2(amp * cv, amp * sv);
    }

    int f = tid >> 6, lane = tid & 63;
    int base = ((b * PM + f) * N + y) * N;
    #pragma unroll
    for (int j = 0; j < 4; j++){
        int x = lane + 64 * j;
        bufA[f][SK(x)] = g_psi[base + x];
    }

    fft256<true>(bufA[f], bufB[f], tw, lane);   // row iFFT (unscaled)

    #pragma unroll
    for (int j = 0; j < 4; j++){
        int x = lane + 64 * j;
        bufA[f][SK(x)] = cmulf(bufA[f][SK(x)], objc[x]);
    }

    fft256<false>(bufA[f], bufB[f], tw, lane);  // row FFT of next fft2

    #pragma unroll
    for (int j = 0; j < 4; j++){
        int x = lane + 64 * j;
        g_psi[base + x] = bufA[f][SK(x)];
    }
}

// ---------------------------------------------------------------------------
// k_final: column FFT + sum over probe modes of |.|^2 -> dp.
// Block = (b, 8 columns), loops over the 4 modes. 512 threads.
// ---------------------------------------------------------------------------
__global__ __launch_bounds__(512) void k_final(float* __restrict__ out)
{
    __shared__ float2 tw[256];
    __shared__ float2 bufA[8][ROWP];
    __shared__ float2 bufB[8][ROWP];

    int tid = threadIdx.x;
    int b   = blockIdx.y;
    int x0  = blockIdx.x * 8;
    fill_tw(tw, tid);

    float acc[4] = {0.f, 0.f, 0.f, 0.f};
    int f = tid >> 6, lane = tid & 63;

    for (int m = 0; m < PM; m++){
        int base = (b * PM + m) * (N * N);
        __syncthreads();
        #pragma unroll
        for (int r = 0; r < 4; r++){
            int e = tid + 512 * r;
            int yy = e >> 3, cc = e & 7;
            bufA[cc][SK(yy)] = g_psi[base + yy * N + x0 + cc];
        }
        fft256<false>(bufA[f], bufB[f], tw, lane);
        #pragma unroll
        for (int r = 0; r < 4; r++){
            int e = tid + 512 * r;
            int yy = e >> 3, cc = e & 7;
            float2 zv = bufA[cc][SK(yy)];
            acc[r] += zv.x * zv.x + zv.y * zv.y;
        }
    }

    #pragma unroll
    for (int r = 0; r < 4; r++){
        int e = tid + 512 * r;
        int yy = e >> 3, cc = e & 7;
        out[b * (N * N) + yy * N + x0 + cc] = acc[r];
    }
}

// ---------------------------------------------------------------------------
// Launch: 16 kernels. inputs (metadata order):
//  0 opt_obj (1,8,1024,1024,2) f32   1 opt_probe (4,256,256,2) f32
//  2 probe_pos_shifts (1024,2) f32   3 crop_pos (1024,2) i32
//  4 H_real (256,256) f32            5 H_imag (256,256) f32
//  6 indices (32,) i32               out: (32,256,256) f32
// ---------------------------------------------------------------------------
extern "C" void kernel_launch(void* const* d_in, const int* in_sizes, int n_in,
                              void* d_out, int out_size)
{
    const float* obj     = (const float*)d_in[0];
    const float* probe   = (const float*)d_in[1];
    const float* shifts  = (const float*)d_in[2];
    const int*   crop    = (const int*)d_in[3];
    const float* Hr      = (const float*)d_in[4];
    const float* Hi      = (const float*)d_in[5];
    const int*   indices = (const int*)d_in[6];
    float* out = (float*)d_out;

    dim3 grow(N, BATCH);      // (y, b)
    dim3 gcol(N / 8, NIMG);   // (colgroup, img)

    k_init<<<grow, 256>>>(obj, probe, shifts, crop, indices);
    for (int z = 1; z < NS; z++){
        k_col<<<gcol, 512>>>(Hr, Hi);
        k_row<<<grow, 256>>>(obj, crop, indices, z);
    }
    k_final<<<dim3(N / 8, BATCH), 512>>>(out);
}

// round 2
// speedup vs baseline: 2.7944x; 2.7944x over previous
#include <cuda_runtime.h>
#include <math.h>

#define N       256
#define BATCH   32
#define PM      4
#define NS      8
#define NIMG    128
#define INV256f (1.0f/256.0f)
#define FSTRIDE 273   // float2 stride per FFT smem buffer (odd => conflict-free both layouts)

// Scratch: psi[img][y][x] complex64, 128*256*256*8B = 64MB
__device__ float2 g_psi[NIMG * N * N];

__device__ __forceinline__ float2 cmul(float2 a, float2 b){
    return make_float2(fmaf(a.x, b.x, -(a.y*b.y)), fmaf(a.x, b.y, a.y*b.x));
}

// W16^E = exp(-2*pi*i*E/16) (forward); conj for inverse
template<int E, bool INV>
__device__ __forceinline__ float2 W16c(){
    constexpr float re[10] = {1.f, 0.92387953251f, 0.70710678119f, 0.38268343236f,
                              0.f, -0.38268343236f, -0.70710678119f, -0.92387953251f,
                              -1.f, -0.92387953251f};
    constexpr float im[10] = {0.f, -0.38268343236f, -0.70710678119f, -0.92387953251f,
                              -1.f, -0.92387953251f, -0.70710678119f, -0.38268343236f,
                              0.f, 0.38268343236f};
    return make_float2(re[E], INV ? -im[E] : im[E]);
}

template<bool INV>
__device__ __forceinline__ void bfly4(float2 a, float2 b, float2 c, float2 d,
                                      float2& o0, float2& o1, float2& o2, float2& o3){
    float2 apc = make_float2(a.x + c.x, a.y + c.y);
    float2 amc = make_float2(a.x - c.x, a.y - c.y);
    float2 bpd = make_float2(b.x + d.x, b.y + d.y);
    float2 bmd = make_float2(b.x - d.x, b.y - d.y);
    o0 = make_float2(apc.x + bpd.x, apc.y + bpd.y);
    o2 = make_float2(apc.x - bpd.x, apc.y - bpd.y);
    if (!INV){
        o1 = make_float2(amc.x + bmd.y, amc.y - bmd.x);   // amc - i*bmd
        o3 = make_float2(amc.x - bmd.y, amc.y + bmd.x);   // amc + i*bmd
    } else {
        o1 = make_float2(amc.x - bmd.y, amc.y + bmd.x);
        o3 = make_float2(amc.x + bmd.y, amc.y - bmd.x);
    }
}

// 16-pt DFT in registers, natural in / natural out.
template<bool INV>
__device__ __forceinline__ void dft16(float2 v[16]){
    float2 u[16];
    #pragma unroll
    for (int n1 = 0; n1 < 4; n1++)
        bfly4<INV>(v[n1], v[n1+4], v[n1+8], v[n1+12],
                   u[n1], u[n1+4], u[n1+8], u[n1+12]);
    // k2 = 0
    bfly4<INV>(u[0], u[1], u[2], u[3], v[0], v[4], v[8], v[12]);
    // k2 = 1
    {
        float2 z1 = cmul(u[5],  W16c<1,INV>());
        float2 z2 = cmul(u[6],  W16c<2,INV>());
        float2 z3 = cmul(u[7],  W16c<3,INV>());
        bfly4<INV>(u[4], z1, z2, z3, v[1], v[5], v[9], v[13]);
    }
    // k2 = 2
    {
        float2 z1 = cmul(u[9],  W16c<2,INV>());
        float2 z2 = cmul(u[10], W16c<4,INV>());
        float2 z3 = cmul(u[11], W16c<6,INV>());
        bfly4<INV>(u[8], z1, z2, z3, v[2], v[6], v[10], v[14]);
    }
    // k2 = 3
    {
        float2 z1 = cmul(u[13], W16c<3,INV>());
        float2 z2 = cmul(u[14], W16c<6,INV>());
        float2 z3 = cmul(u[15], W16c<9,INV>());
        bfly4<INV>(u[12], z1, z2, z3, v[3], v[7], v[11], v[15]);
    }
}

// 256-pt FFT: 16 threads cooperate; thread t holds element (t + 16*j) in v[j]
// on input AND output (layout A). One smem transpose; buf = per-FFT base,
// inner row stride 17 float2.
template<bool INV>
__device__ __forceinline__ void fft256r(float2 v[16], float2* buf, int t){
    dft16<INV>(v);
    // twiddles W256^{-+ t*k2} via repeated squaring from one sincospif
    float s, c;
    sincospif((float)t * (INV ? (1.0f/128.0f) : (-1.0f/128.0f)), &s, &c);
    float2 w1  = make_float2(c, s);
    float2 w2  = cmul(w1, w1);
    float2 w3  = cmul(w2, w1);
    float2 w4  = cmul(w2, w2);
    float2 w8  = cmul(w4, w4);
    float2 w12 = cmul(w8, w4);
    v[1]  = cmul(v[1],  w1);
    v[2]  = cmul(v[2],  w2);
    v[3]  = cmul(v[3],  w3);
    v[4]  = cmul(v[4],  w4);
    v[5]  = cmul(v[5],  cmul(w4, w1));
    v[6]  = cmul(v[6],  cmul(w4, w2));
    v[7]  = cmul(v[7],  cmul(w4, w3));
    v[8]  = cmul(v[8],  w8);
    v[9]  = cmul(v[9],  cmul(w8, w1));
    v[10] = cmul(v[10], cmul(w8, w2));
    v[11] = cmul(v[11], cmul(w8, w3));
    v[12] = cmul(v[12], w12);
    v[13] = cmul(v[13], cmul(w12, w1));
    v[14] = cmul(v[14], cmul(w12, w2));
    v[15] = cmul(v[15], cmul(w12, w3));
    __syncthreads();
    #pragma unroll
    for (int k2 = 0; k2 < 16; k2++) buf[k2*17 + t] = v[k2];
    __syncthreads();
    #pragma unroll
    for (int n1 = 0; n1 < 16; n1++) v[n1] = buf[t*17 + n1];
    dft16<INV>(v);
}

// ---------------------------------------------------------------------------
// k_init: probe translate * obj[z=0] -> row FFT. Block: 16 rows of one image.
// t-low layout (t = lane, f = row). grid (16, 128)
// ---------------------------------------------------------------------------
__global__ __launch_bounds__(256) void k_init(
    const float* __restrict__ obj, const float* __restrict__ probe,
    const float* __restrict__ shifts, const int* __restrict__ crop,
    const int* __restrict__ indices)
{
    __shared__ float2 buf[16 * FSTRIDE];
    int tid = threadIdx.x;
    int t = tid & 15, f = tid >> 4;
    int img = blockIdx.y;
    int b = img >> 2, m = img & 3;
    int y = (blockIdx.x << 4) + f;
    int idx = indices[b];
    int p0 = crop[2*idx], p1 = crop[2*idx + 1];
    float sH = shifts[2*idx], sW = shifts[2*idx + 1];

    float fy = -sH, fx = -sW;
    float Fy = floorf(fy), Fx = floorf(fx);
    int ky = (int)Fy, kx = (int)Fx;
    float wy = fy - Fy, wx = fx - Fx;
    int r0 = y + ky, r1 = r0 + 1;
    bool vy0 = (r0 >= 0 && r0 < 256), vy1 = (r1 >= 0 && r1 < 256);
    int r0c = min(max(r0, 0), 255), r1c = min(max(r1, 0), 255);

    const float2* P = (const float2*)probe + m * 65536;
    const float2* orow = (const float2*)obj + (size_t)(p0 + y) * 1024 + p1;

    float2 v[16];
    #pragma unroll
    for (int j = 0; j < 16; j++){
        int x = t + 16*j;
        int c0 = x + kx, c1 = c0 + 1;
        bool vx0 = (c0 >= 0 && c0 < 256), vx1 = (c1 >= 0 && c1 < 256);
        int c0c = min(max(c0, 0), 255), c1c = min(max(c1, 0), 255);
        float w00 = (1.0f - wy) * (1.0f - wx) * ((vy0 && vx0) ? 1.0f : 0.0f);
        float w01 = (1.0f - wy) * wx          * ((vy0 && vx1) ? 1.0f : 0.0f);
        float w10 = wy * (1.0f - wx)          * ((vy1 && vx0) ? 1.0f : 0.0f);
        float w11 = wy * wx                   * ((vy1 && vx1) ? 1.0f : 0.0f);
        float2 a00 = P[r0c*256 + c0c], a01 = P[r0c*256 + c1c];
        float2 a10 = P[r1c*256 + c0c], a11 = P[r1c*256 + c1c];
        float amp = w00*a00.x + w01*a01.x + w10*a10.x + w11*a11.x;
        float ph  = w00*a00.y + w01*a01.y + w10*a10.y + w11*a11.y;
        float sv, cv; sincosf(ph, &sv, &cv);
        float2 pc = make_float2(amp*cv, amp*sv);
        float2 ov = orow[x];
        float so, co; sincosf(ov.y, &so, &co);
        v[j] = cmul(pc, make_float2(ov.x*co, ov.x*so));
    }

    fft256r<false>(v, buf + f*FSTRIDE, t);

    float2* q = g_psi + img*65536 + y*256;
    #pragma unroll
    for (int j = 0; j < 16; j++) q[t + 16*j] = v[j];
}

// ---------------------------------------------------------------------------
// k_col: col FFT -> *(H/256) -> col iFFT. Block: 16 cols of one image.
// f-low layout (f = column, t = lane). grid (16, 128)
// ---------------------------------------------------------------------------
__global__ __launch_bounds__(256) void k_col(
    const float* __restrict__ Hr, const float* __restrict__ Hi)
{
    __shared__ float2 buf[16 * FSTRIDE];
    int tid = threadIdx.x;
    int f = tid & 15, t = tid >> 4;
    int img = blockIdx.y;
    int x = (blockIdx.x << 4) + f;
    float2* fb = buf + f*FSTRIDE;

    float2 v[16];
    float2* p = g_psi + img*65536 + x;
    #pragma unroll
    for (int j = 0; j < 16; j++) v[j] = p[(t + 16*j)*256];

    fft256r<false>(v, fb, t);

    #pragma unroll
    for (int k1 = 0; k1 < 16; k1++){
        int kyy = 16*k1 + t;
        float hr = Hr[kyy*256 + x] * INV256f;
        float hi = Hi[kyy*256 + x] * INV256f;
        v[k1] = cmul(v[k1], make_float2(hr, hi));
    }

    fft256r<true>(v, fb, t);

    #pragma unroll
    for (int j = 0; j < 16; j++) p[(t + 16*j)*256] = v[j];
}

// ---------------------------------------------------------------------------
// k_row: row iFFT -> *(obj_z/256) -> row FFT. Block: 16 rows of one image.
// t-low layout. grid (16, 128)
// ---------------------------------------------------------------------------
__global__ __launch_bounds__(256) void k_row(
    const float* __restrict__ obj, const int* __restrict__ crop,
    const int* __restrict__ indices, int z)
{
    __shared__ float2 buf[16 * FSTRIDE];
    int tid = threadIdx.x;
    int t = tid & 15, f = tid >> 4;
    int img = blockIdx.y;
    int b = img >> 2;
    int y = (blockIdx.x << 4) + f;
    int idx = indices[b];
    int p0 = crop[2*idx], p1 = crop[2*idx + 1];
    float2* fb = buf + f*FSTRIDE;

    float2 v[16];
    float2* p = g_psi + img*65536 + y*256;
    #pragma unroll
    for (int j = 0; j < 16; j++) v[j] = p[t + 16*j];

    fft256r<true>(v, fb, t);   // row iFFT (scale folded into obj)

    const float2* orow = (const float2*)obj + (size_t)(z*1024 + p0 + y)*1024 + p1;
    #pragma unroll
    for (int j = 0; j < 16; j++){
        int xx = t + 16*j;
        float2 ov = orow[xx];
        float amp = ov.x * INV256f;
        float sv, cv; sincosf(ov.y, &sv, &cv);
        v[j] = cmul(v[j], make_float2(amp*cv, amp*sv));
    }

    fft256r<false>(v, fb, t);  // row FFT of next fft2

    #pragma unroll
    for (int j = 0; j < 16; j++) p[t + 16*j] = v[j];
}

// ---------------------------------------------------------------------------
// k_final: col FFT + sum_m |.|^2. Block: 16 cols, loop 4 modes. grid (16, 32)
// ---------------------------------------------------------------------------
__global__ __launch_bounds__(256) void k_final(float* __restrict__ out)
{
    __shared__ float2 buf[16 * FSTRIDE];
    int tid = threadIdx.x;
    int f = tid & 15, t = tid >> 4;
    int b = blockIdx.y;
    int x = (blockIdx.x << 4) + f;
    float2* fb = buf + f*FSTRIDE;

    float acc[16];
    #pragma unroll
    for (int k1 = 0; k1 < 16; k1++) acc[k1] = 0.f;

    for (int m = 0; m < PM; m++){
        const float2* p = g_psi + (b*4 + m)*65536 + x;
        float2 v[16];
        #pragma unroll
        for (int j = 0; j < 16; j++) v[j] = p[(t + 16*j)*256];
        fft256r<false>(v, fb, t);
        #pragma unroll
        for (int k1 = 0; k1 < 16; k1++)
            acc[k1] += v[k1].x*v[k1].x + v[k1].y*v[k1].y;
    }

    #pragma unroll
    for (int k1 = 0; k1 < 16; k1++){
        int kyy = 16*k1 + t;
        out[b*65536 + kyy*256 + x] = acc[k1];
    }
}

// ---------------------------------------------------------------------------
// inputs: 0 obj (1,8,1024,1024,2) f32 | 1 probe (4,256,256,2) f32
//         2 shifts (1024,2) f32 | 3 crop (1024,2) i32
//         4 H_real | 5 H_imag (256,256) f32 | 6 indices (32,) i32
// out: (32,256,256) f32
// ---------------------------------------------------------------------------
extern "C" void kernel_launch(void* const* d_in, const int* in_sizes, int n_in,
                              void* d_out, int out_size)
{
    const float* obj     = (const float*)d_in[0];
    const float* probe   = (const float*)d_in[1];
    const float* shifts  = (const float*)d_in[2];
    const int*   crop    = (const int*)d_in[3];
    const float* Hr      = (const float*)d_in[4];
    const float* Hi      = (const float*)d_in[5];
    const int*   indices = (const int*)d_in[6];
    float* out = (float*)d_out;

    dim3 g(16, NIMG);

    k_init<<<g, 256>>>(obj, probe, shifts, crop, indices);
    for (int z = 1; z < NS; z++){
        k_col<<<g, 256>>>(Hr, Hi);
        k_row<<<g, 256>>>(obj, crop, indices, z);
    }
    k_final<<<dim3(16, BATCH), 256>>>(out);
}

// round 7
// speedup vs baseline: 3.4921x; 1.2497x over previous
#include <cuda_runtime.h>
#include <math.h>

#define N       256
#define BATCH   32
#define PM      4
#define NS      8
#define NIMG    128
#define INV256f (1.0f/256.0f)
#define FSTRIDE 273   // float2 stride per FFT smem buffer

// Scratch: psi[img][y][x] complex64, 128*256*256*8B = 64MB
__device__ float2 g_psi[NIMG * N * N];

__device__ __forceinline__ float2 cmul(float2 a, float2 b){
    return make_float2(fmaf(a.x, b.x, -(a.y*b.y)), fmaf(a.x, b.y, a.y*b.x));
}

// ---- radix-16x16 FFT pieces -----------------------------------------------
template<int E, bool INV>
__device__ __forceinline__ float2 W16c(){
    constexpr float re[10] = {1.f, 0.92387953251f, 0.70710678119f, 0.38268343236f,
                              0.f, -0.38268343236f, -0.70710678119f, -0.92387953251f,
                              -1.f, -0.92387953251f};
    constexpr float im[10] = {0.f, -0.38268343236f, -0.70710678119f, -0.92387953251f,
                              -1.f, -0.92387953251f, -0.70710678119f, -0.38268343236f,
                              0.f, 0.38268343236f};
    return make_float2(re[E], INV ? -im[E] : im[E]);
}

template<bool INV>
__device__ __forceinline__ void bfly4(float2 a, float2 b, float2 c, float2 d,
                                      float2& o0, float2& o1, float2& o2, float2& o3){
    float2 apc = make_float2(a.x + c.x, a.y + c.y);
    float2 amc = make_float2(a.x - c.x, a.y - c.y);
    float2 bpd = make_float2(b.x + d.x, b.y + d.y);
    float2 bmd = make_float2(b.x - d.x, b.y - d.y);
    o0 = make_float2(apc.x + bpd.x, apc.y + bpd.y);
    o2 = make_float2(apc.x - bpd.x, apc.y - bpd.y);
    if (!INV){
        o1 = make_float2(amc.x + bmd.y, amc.y - bmd.x);
        o3 = make_float2(amc.x - bmd.y, amc.y + bmd.x);
    } else {
        o1 = make_float2(amc.x - bmd.y, amc.y + bmd.x);
        o3 = make_float2(amc.x + bmd.y, amc.y - bmd.x);
    }
}

template<bool INV>
__device__ __forceinline__ void dft16(float2 v[16]){
    float2 u[16];
    #pragma unroll
    for (int n1 = 0; n1 < 4; n1++)
        bfly4<INV>(v[n1], v[n1+4], v[n1+8], v[n1+12],
                   u[n1], u[n1+4], u[n1+8], u[n1+12]);
    bfly4<INV>(u[0], u[1], u[2], u[3], v[0], v[4], v[8], v[12]);
    {
        float2 z1 = cmul(u[5],  W16c<1,INV>());
        float2 z2 = cmul(u[6],  W16c<2,INV>());
        float2 z3 = cmul(u[7],  W16c<3,INV>());
        bfly4<INV>(u[4], z1, z2, z3, v[1], v[5], v[9], v[13]);
    }
    {
        float2 z1 = cmul(u[9],  W16c<2,INV>());
        float2 z2 = cmul(u[10], W16c<4,INV>());
        float2 z3 = cmul(u[11], W16c<6,INV>());
        bfly4<INV>(u[8], z1, z2, z3, v[2], v[6], v[10], v[14]);
    }
    {
        float2 z1 = cmul(u[13], W16c<3,INV>());
        float2 z2 = cmul(u[14], W16c<6,INV>());
        float2 z3 = cmul(u[15], W16c<9,INV>());
        bfly4<INV>(u[12], z1, z2, z3, v[3], v[7], v[11], v[15]);
    }
}

// fill 16x16 forward twiddle table, stride 17 (bank-conflict-free).
// tw[t*17+k] = exp(-2*pi*i*t*k/256). Caller must __syncthreads() after.
__device__ __forceinline__ void fill_tw(float2* tw, int tid){
    int tt = tid >> 4, kk = tid & 15;
    float s, c;
    sincospif(-(float)(tt * kk) * (1.0f/128.0f), &s, &c);
    tw[tt*17 + kk] = make_float2(c, s);
}

// 256-pt FFT: 16 threads; thread t holds element (t + 16*j) in v[j] in & out.
template<bool INV>
__device__ __forceinline__ void fft256r(float2 v[16], float2* buf,
                                        const float2* tw, int t){
    dft16<INV>(v);
    const float2* twr = tw + t*17;
    #pragma unroll
    for (int k2 = 1; k2 < 16; k2++){
        float2 w = twr[k2];
        if (INV) w.y = -w.y;
        v[k2] = cmul(v[k2], w);
    }
    __syncthreads();
    #pragma unroll
    for (int k2 = 0; k2 < 16; k2++) buf[k2*17 + t] = v[k2];
    __syncthreads();
    #pragma unroll
    for (int n1 = 0; n1 < 16; n1++) v[n1] = buf[t*17 + n1];
    dft16<INV>(v);
}

// ---------------------------------------------------------------------------
// k_init: probe translate * obj[z=0] -> row FFT.
// CTA: 4 rows x 4 modes of one batch. unit u: m=u>>2, r=u&3. grid (64, 32).
// ---------------------------------------------------------------------------
__global__ __launch_bounds__(256) void k_init(
    const float* __restrict__ obj, const float* __restrict__ probe,
    const float* __restrict__ shifts, const int* __restrict__ crop,
    const int* __restrict__ indices)
{
    __shared__ float2 tw[16*17];
    __shared__ float2 objc[4][260];
    __shared__ float2 buf[16*FSTRIDE];

    int tid = threadIdx.x;
    fill_tw(tw, tid);

    int b  = blockIdx.y;
    int y0 = blockIdx.x << 2;
    int idx = indices[b];
    int p0 = crop[2*idx], p1 = crop[2*idx + 1];
    float sH = shifts[2*idx], sW = shifts[2*idx + 1];

    // convert obj rows y0..y0+3 (slice 0) into smem, shared by all 4 modes
    const float2* ob = (const float2*)obj + (size_t)(p0 + y0) * 1024 + p1;
    #pragma unroll
    for (int i = 0; i < 4; i++){
        int e = tid + 256*i; int rr = e >> 8; int xx = e & 255;
        float2 ov = __ldcs(ob + (size_t)rr*1024 + xx);   // streaming
        float sv, cv; sincosf(ov.y, &sv, &cv);
        objc[rr][xx] = make_float2(ov.x*cv, ov.x*sv);
    }
    __syncthreads();

    int t = tid & 15, u = tid >> 4;
    int m = u >> 2, r = u & 3;
    int y = y0 + r;

    // bilinear constants
    float fy = -sH, fx = -sW;
    float Fy = floorf(fy), Fx = floorf(fx);
    int ky = (int)Fy, kx = (int)Fx;
    float wy = fy - Fy, wx = fx - Fx;
    int r0 = y + ky, r1 = r0 + 1;
    bool vy0 = (r0 >= 0 && r0 < 256), vy1 = (r1 >= 0 && r1 < 256);
    int r0c = min(max(r0, 0), 255), r1c = min(max(r1, 0), 255);
    const float2* P = (const float2*)probe + m * 65536;

    float2 v[16];
    #pragma unroll
    for (int j = 0; j < 16; j++){
        int x = t + 16*j;
        int c0 = x + kx, c1 = c0 + 1;
        bool vx0 = (c0 >= 0 && c0 < 256), vx1 = (c1 >= 0 && c1 < 256);
        int c0c = min(max(c0, 0), 255), c1c = min(max(c1, 0), 255);
        float w00 = (1.0f - wy) * (1.0f - wx) * ((vy0 && vx0) ? 1.0f : 0.0f);
        float w01 = (1.0f - wy) * wx          * ((vy0 && vx1) ? 1.0f : 0.0f);
        float w10 = wy * (1.0f - wx)          * ((vy1 && vx0) ? 1.0f : 0.0f);
        float w11 = wy * wx                   * ((vy1 && vx1) ? 1.0f : 0.0f);
        float2 a00 = __ldg(P + r0c*256 + c0c), a01 = __ldg(P + r0c*256 + c1c);
        float2 a10 = __ldg(P + r1c*256 + c0c), a11 = __ldg(P + r1c*256 + c1c);
        float amp = w00*a00.x + w01*a01.x + w10*a10.x + w11*a11.x;
        float ph  = w00*a00.y + w01*a01.y + w10*a10.y + w11*a11.y;
        float sv, cv; sincosf(ph, &sv, &cv);
        float2 pc = make_float2(amp*cv, amp*sv);
        v[j] = cmul(pc, objc[r][x]);
    }

    fft256r<false>(v, buf + u*FSTRIDE, tw, t);

    float2* q = g_psi + (b*4 + m)*65536 + y*256;
    #pragma unroll
    for (int j = 0; j < 16; j++) q[t + 16*j] = v[j];
}

// ---------------------------------------------------------------------------
// k_col: col FFT -> *(H/256) -> col iFFT. 16 cols of one image. grid (16,128)
// ---------------------------------------------------------------------------
__global__ __launch_bounds__(256) void k_col(
    const float* __restrict__ Hr, const float* __restrict__ Hi)
{
    __shared__ float2 tw[16*17];
    __shared__ float2 buf[16*FSTRIDE];

    int tid = threadIdx.x;
    fill_tw(tw, tid);
    __syncthreads();

    int f = tid & 15, t = tid >> 4;
    int img = blockIdx.y;
    int x = (blockIdx.x << 4) + f;
    float2* fb = buf + f*FSTRIDE;

    float2 v[16];
    float2* p = g_psi + img*65536 + x;
    #pragma unroll
    for (int j = 0; j < 16; j++) v[j] = p[(t + 16*j)*256];

    fft256r<false>(v, fb, tw, t);

    #pragma unroll
    for (int k1 = 0; k1 < 16; k1++){
        int kyy = 16*k1 + t;
        float hr = __ldg(Hr + kyy*256 + x) * INV256f;
        float hi = __ldg(Hi + kyy*256 + x) * INV256f;
        v[k1] = cmul(v[k1], make_float2(hr, hi));
    }

    fft256r<true>(v, fb, tw, t);

    #pragma unroll
    for (int j = 0; j < 16; j++) p[(t + 16*j)*256] = v[j];
}

// ---------------------------------------------------------------------------
// k_row: row iFFT -> *(obj_z/256) -> row FFT.
// CTA: 4 rows x 4 modes of one batch; obj converted once in smem. grid (64,32)
// ---------------------------------------------------------------------------
__global__ __launch_bounds__(256) void k_row(
    const float* __restrict__ obj, const int* __restrict__ crop,
    const int* __restrict__ indices, int z)
{
    __shared__ float2 tw[16*17];
    __shared__ float2 objc[4][260];
    __shared__ float2 buf[16*FSTRIDE];

    int tid = threadIdx.x;
    fill_tw(tw, tid);

    int b  = blockIdx.y;
    int y0 = blockIdx.x << 2;
    int idx = indices[b];
    int p0 = crop[2*idx], p1 = crop[2*idx + 1];

    const float2* ob = (const float2*)obj + (size_t)(z*1024 + p0 + y0)*1024 + p1;
    #pragma unroll
    for (int i = 0; i < 4; i++){
        int e = tid + 256*i; int rr = e >> 8; int xx = e & 255;
        float2 ov = __ldcs(ob + (size_t)rr*1024 + xx);   // streaming
        float sv, cv; sincosf(ov.y, &sv, &cv);
        float amp = ov.x * INV256f;          // fold ifft row scale
        objc[rr][xx] = make_float2(amp*cv, amp*sv);
    }
    __syncthreads();

    int t = tid & 15, u = tid >> 4;
    int m = u >> 2, r = u & 3;
    float2* p = g_psi + (b*4 + m)*65536 + (y0 + r)*256;
    float2* fb = buf + u*FSTRIDE;

    float2 v[16];
    #pragma unroll
    for (int j = 0; j < 16; j++) v[j] = p[t + 16*j];

    fft256r<true>(v, fb, tw, t);

    #pragma unroll
    for (int j = 0; j < 16; j++) v[j] = cmul(v[j], objc[r][t + 16*j]);

    fft256r<false>(v, fb, tw, t);

    #pragma unroll
    for (int j = 0; j < 16; j++) p[t + 16*j] = v[j];
}

// ---------------------------------------------------------------------------
// k_final: col FFT + sum_m |.|^2. 16 cols, loop 4 modes. grid (16, 32)
// ---------------------------------------------------------------------------
__global__ __launch_bounds__(256) void k_final(float* __restrict__ out)
{
    __shared__ float2 tw[16*17];
    __shared__ float2 buf[16*FSTRIDE];

    int tid = threadIdx.x;
    fill_tw(tw, tid);
    __syncthreads();

    int f = tid & 15, t = tid >> 4;
    int b = blockIdx.y;
    int x = (blockIdx.x << 4) + f;
    float2* fb = buf + f*FSTRIDE;

    float acc[16];
    #pragma unroll
    for (int k1 = 0; k1 < 16; k1++) acc[k1] = 0.f;

    for (int m = 0; m < PM; m++){
        const float2* p = g_psi + (b*4 + m)*65536 + x;
        float2 v[16];
        #pragma unroll
        for (int j = 0; j < 16; j++) v[j] = p[(t + 16*j)*256];
        fft256r<false>(v, fb, tw, t);
        #pragma unroll
        for (int k1 = 0; k1 < 16; k1++)
            acc[k1] += v[k1].x*v[k1].x + v[k1].y*v[k1].y;
    }

    #pragma unroll
    for (int k1 = 0; k1 < 16; k1++){
        int kyy = 16*k1 + t;
        out[b*65536 + kyy*256 + x] = acc[k1];
    }
}

// ---------------------------------------------------------------------------
extern "C" void kernel_launch(void* const* d_in, const int* in_sizes, int n_in,
                              void* d_out, int out_size)
{
    const float* obj     = (const float*)d_in[0];
    const float* probe   = (const float*)d_in[1];
    const float* shifts  = (const float*)d_in[2];
    const int*   crop    = (const int*)d_in[3];
    const float* Hr      = (const float*)d_in[4];
    const float* Hi      = (const float*)d_in[5];
    const int*   indices = (const int*)d_in[6];
    float* out = (float*)d_out;

    dim3 grow(64, BATCH);     // 4 rows x 4 modes per CTA
    dim3 gcol(16, NIMG);

    k_init<<<grow, 256>>>(obj, probe, shifts, crop, indices);
    for (int z = 1; z < NS; z++){
        k_col<<<gcol, 256>>>(Hr, Hi);
        k_row<<<grow, 256>>>(obj, crop, indices, z);
    }
    k_final<<<dim3(16, BATCH), 256>>>(out);
}

// round 8
// speedup vs baseline: 3.6665x; 1.0499x over previous
#include <cuda_runtime.h>
#include <math.h>

#define N       256
#define BATCH   32
#define PM      4
#define NS      8
#define NIMG    128
#define INV256f (1.0f/256.0f)
#define FSTRIDE 273   // float2 stride per FFT smem buffer

// Scratch: psi[img][y][x] complex64, 128*256*256*8B = 64MB
__device__ float2 g_psi[NIMG * N * N];

__device__ __forceinline__ float2 cmul(float2 a, float2 b){
    return make_float2(fmaf(a.x, b.x, -(a.y*b.y)), fmaf(a.x, b.y, a.y*b.x));
}

// ---- radix-16x16 FFT pieces -----------------------------------------------
template<int E, bool INV>
__device__ __forceinline__ float2 W16c(){
    constexpr float re[10] = {1.f, 0.92387953251f, 0.70710678119f, 0.38268343236f,
                              0.f, -0.38268343236f, -0.70710678119f, -0.92387953251f,
                              -1.f, -0.92387953251f};
    constexpr float im[10] = {0.f, -0.38268343236f, -0.70710678119f, -0.92387953251f,
                              -1.f, -0.92387953251f, -0.70710678119f, -0.38268343236f,
                              0.f, 0.38268343236f};
    return make_float2(re[E], INV ? -im[E] : im[E]);
}

template<bool INV>
__device__ __forceinline__ void bfly4(float2 a, float2 b, float2 c, float2 d,
                                      float2& o0, float2& o1, float2& o2, float2& o3){
    float2 apc = make_float2(a.x + c.x, a.y + c.y);
    float2 amc = make_float2(a.x - c.x, a.y - c.y);
    float2 bpd = make_float2(b.x + d.x, b.y + d.y);
    float2 bmd = make_float2(b.x - d.x, b.y - d.y);
    o0 = make_float2(apc.x + bpd.x, apc.y + bpd.y);
    o2 = make_float2(apc.x - bpd.x, apc.y - bpd.y);
    if (!INV){
        o1 = make_float2(amc.x + bmd.y, amc.y - bmd.x);
        o3 = make_float2(amc.x - bmd.y, amc.y + bmd.x);
    } else {
        o1 = make_float2(amc.x - bmd.y, amc.y + bmd.x);
        o3 = make_float2(amc.x + bmd.y, amc.y - bmd.x);
    }
}

template<bool INV>
__device__ __forceinline__ void dft16(float2 v[16]){
    float2 u[16];
    #pragma unroll
    for (int n1 = 0; n1 < 4; n1++)
        bfly4<INV>(v[n1], v[n1+4], v[n1+8], v[n1+12],
                   u[n1], u[n1+4], u[n1+8], u[n1+12]);
    bfly4<INV>(u[0], u[1], u[2], u[3], v[0], v[4], v[8], v[12]);
    {
        float2 z1 = cmul(u[5],  W16c<1,INV>());
        float2 z2 = cmul(u[6],  W16c<2,INV>());
        float2 z3 = cmul(u[7],  W16c<3,INV>());
        bfly4<INV>(u[4], z1, z2, z3, v[1], v[5], v[9], v[13]);
    }
    {
        float2 z1 = cmul(u[9],  W16c<2,INV>());
        // W16^4 = -i (fwd) / +i (inv): free multiply
        float2 z2 = INV ? make_float2(-u[10].y, u[10].x)
                        : make_float2(u[10].y, -u[10].x);
        float2 z3 = cmul(u[11], W16c<6,INV>());
        bfly4<INV>(u[8], z1, z2, z3, v[2], v[6], v[10], v[14]);
    }
    {
        float2 z1 = cmul(u[13], W16c<3,INV>());
        float2 z2 = cmul(u[14], W16c<6,INV>());
        float2 z3 = cmul(u[15], W16c<9,INV>());
        bfly4<INV>(u[12], z1, z2, z3, v[3], v[7], v[11], v[15]);
    }
}

// fill 16x16 forward twiddle table, stride 17 (bank-conflict-free).
// tw[t*17+k] = exp(-2*pi*i*t*k/256). Caller must sync after.
__device__ __forceinline__ void fill_tw(float2* tw, int tid){
    int tt = tid >> 4, kk = tid & 15;
    float s, c;
    sincospif(-(float)(tt * kk) * (1.0f/128.0f), &s, &c);
    tw[tt*17 + kk] = make_float2(c, s);
}

// 256-pt FFT: 16 threads; thread t holds element (t + 16*j) in v[j] in & out.
// BLK=true: FFT lanes span warps -> __syncthreads (lead skippable if buf idle).
// BLK=false: FFT lanes within one half-warp, per-unit buf -> __syncwarp only.
template<bool INV, bool BLK>
__device__ __forceinline__ void fft256r(float2 v[16], float2* buf,
                                        const float2* tw, int t, bool lead = true){
    dft16<INV>(v);
    const float2* twr = tw + t*17;
    #pragma unroll
    for (int k2 = 1; k2 < 16; k2++){
        float2 w = twr[k2];
        if (INV) w.y = -w.y;
        v[k2] = cmul(v[k2], w);
    }
    if (BLK){ if (lead) __syncthreads(); } else __syncwarp();
    #pragma unroll
    for (int k2 = 0; k2 < 16; k2++) buf[k2*17 + t] = v[k2];
    if (BLK) __syncthreads(); else __syncwarp();
    #pragma unroll
    for (int n1 = 0; n1 < 16; n1++) v[n1] = buf[t*17 + n1];
    dft16<INV>(v);
}

// ---------------------------------------------------------------------------
// k_init: probe translate * obj[z=0] -> row FFT.
// CTA: 4 rows x 4 modes of one batch. unit u: m=u>>2, r=u&3. grid (64, 32).
// t-low layout: warp-local FFTs.
// ---------------------------------------------------------------------------
__global__ __launch_bounds__(256) void k_init(
    const float* __restrict__ obj, const float* __restrict__ probe,
    const float* __restrict__ shifts, const int* __restrict__ crop,
    const int* __restrict__ indices)
{
    __shared__ float2 tw[16*17];
    __shared__ float2 objc[4][260];
    __shared__ float2 buf[16*FSTRIDE];

    int tid = threadIdx.x;
    fill_tw(tw, tid);

    int b  = blockIdx.y;
    int y0 = blockIdx.x << 2;
    int idx = indices[b];
    int p0 = crop[2*idx], p1 = crop[2*idx + 1];
    float sH = shifts[2*idx], sW = shifts[2*idx + 1];

    // convert obj rows y0..y0+3 (slice 0) into smem, shared by all 4 modes
    const float2* ob = (const float2*)obj + (size_t)(p0 + y0) * 1024 + p1;
    #pragma unroll
    for (int i = 0; i < 4; i++){
        int e = tid + 256*i; int rr = e >> 8; int xx = e & 255;
        float2 ov = __ldcs(ob + (size_t)rr*1024 + xx);   // streaming
        float sv, cv; sincosf(ov.y, &sv, &cv);
        objc[rr][xx] = make_float2(ov.x*cv, ov.x*sv);
    }
    __syncthreads();   // objc + tw ready

    int t = tid & 15, u = tid >> 4;
    int m = u >> 2, r = u & 3;
    int y = y0 + r;

    // bilinear constants
    float fy = -sH, fx = -sW;
    float Fy = floorf(fy), Fx = floorf(fx);
    int ky = (int)Fy, kx = (int)Fx;
    float wy = fy - Fy, wx = fx - Fx;
    int r0 = y + ky, r1 = r0 + 1;
    bool vy0 = (r0 >= 0 && r0 < 256), vy1 = (r1 >= 0 && r1 < 256);
    int r0c = min(max(r0, 0), 255), r1c = min(max(r1, 0), 255);
    const float2* P = (const float2*)probe + m * 65536;

    float2 v[16];
    #pragma unroll
    for (int j = 0; j < 16; j++){
        int x = t + 16*j;
        int c0 = x + kx, c1 = c0 + 1;
        bool vx0 = (c0 >= 0 && c0 < 256), vx1 = (c1 >= 0 && c1 < 256);
        int c0c = min(max(c0, 0), 255), c1c = min(max(c1, 0), 255);
        float w00 = (1.0f - wy) * (1.0f - wx) * ((vy0 && vx0) ? 1.0f : 0.0f);
        float w01 = (1.0f - wy) * wx          * ((vy0 && vx1) ? 1.0f : 0.0f);
        float w10 = wy * (1.0f - wx)          * ((vy1 && vx0) ? 1.0f : 0.0f);
        float w11 = wy * wx                   * ((vy1 && vx1) ? 1.0f : 0.0f);
        float2 a00 = __ldg(P + r0c*256 + c0c), a01 = __ldg(P + r0c*256 + c1c);
        float2 a10 = __ldg(P + r1c*256 + c0c), a11 = __ldg(P + r1c*256 + c1c);
        float amp = w00*a00.x + w01*a01.x + w10*a10.x + w11*a11.x;
        float ph  = w00*a00.y + w01*a01.y + w10*a10.y + w11*a11.y;
        float sv, cv; sincosf(ph, &sv, &cv);
        float2 pc = make_float2(amp*cv, amp*sv);
        v[j] = cmul(pc, objc[r][x]);
    }

    fft256r<false,false>(v, buf + u*FSTRIDE, tw, t);

    float2* q = g_psi + (b*4 + m)*65536 + y*256;
    #pragma unroll
    for (int j = 0; j < 16; j++) q[t + 16*j] = v[j];
}

// ---------------------------------------------------------------------------
// k_col: col FFT -> *(H/256) -> col iFFT. 16 cols of one image. grid (16,128)
// f-low layout (coalesced column access); block-sync FFTs, lead elided on #1.
// ---------------------------------------------------------------------------
__global__ __launch_bounds__(256) void k_col(
    const float* __restrict__ Hr, const float* __restrict__ Hi)
{
    __shared__ float2 tw[16*17];
    __shared__ float2 buf[16*FSTRIDE];

    int tid = threadIdx.x;
    fill_tw(tw, tid);
    __syncthreads();

    int f = tid & 15, t = tid >> 4;
    int img = blockIdx.y;
    int x = (blockIdx.x << 4) + f;
    float2* fb = buf + f*FSTRIDE;

    float2 v[16];
    float2* p = g_psi + img*65536 + x;
    #pragma unroll
    for (int j = 0; j < 16; j++) v[j] = p[(t + 16*j)*256];

    fft256r<false,true>(v, fb, tw, t, false);  // buf untouched yet

    #pragma unroll
    for (int k1 = 0; k1 < 16; k1++){
        int kyy = 16*k1 + t;
        float hr = __ldg(Hr + kyy*256 + x) * INV256f;
        float hi = __ldg(Hi + kyy*256 + x) * INV256f;
        v[k1] = cmul(v[k1], make_float2(hr, hi));
    }

    fft256r<true,true>(v, fb, tw, t, true);

    #pragma unroll
    for (int j = 0; j < 16; j++) p[(t + 16*j)*256] = v[j];
}

// ---------------------------------------------------------------------------
// k_row: row iFFT -> *(obj_z/256) -> row FFT.
// CTA: 4 rows x 4 modes of one batch; obj converted once in smem. grid (64,32)
// t-low layout: warp-local FFTs, no block syncs after objc barrier.
// ---------------------------------------------------------------------------
__global__ __launch_bounds__(256) void k_row(
    const float* __restrict__ obj, const int* __restrict__ crop,
    const int* __restrict__ indices, int z)
{
    __shared__ float2 tw[16*17];
    __shared__ float2 objc[4][260];
    __shared__ float2 buf[16*FSTRIDE];

    int tid = threadIdx.x;
    fill_tw(tw, tid);

    int b  = blockIdx.y;
    int y0 = blockIdx.x << 2;
    int idx = indices[b];
    int p0 = crop[2*idx], p1 = crop[2*idx + 1];

    const float2* ob = (const float2*)obj + (size_t)(z*1024 + p0 + y0)*1024 + p1;
    #pragma unroll
    for (int i = 0; i < 4; i++){
        int e = tid + 256*i; int rr = e >> 8; int xx = e & 255;
        float2 ov = __ldcs(ob + (size_t)rr*1024 + xx);   // streaming
        float sv, cv; sincosf(ov.y, &sv, &cv);
        float amp = ov.x * INV256f;          // fold ifft row scale
        objc[rr][xx] = make_float2(amp*cv, amp*sv);
    }
    __syncthreads();   // objc + tw ready

    int t = tid & 15, u = tid >> 4;
    int m = u >> 2, r = u & 3;
    float2* p = g_psi + (b*4 + m)*65536 + (y0 + r)*256;
    float2* fb = buf + u*FSTRIDE;

    float2 v[16];
    #pragma unroll
    for (int j = 0; j < 16; j++) v[j] = p[t + 16*j];

    fft256r<true,false>(v, fb, tw, t);   // row iFFT (scale folded into obj)

    #pragma unroll
    for (int j = 0; j < 16; j++) v[j] = cmul(v[j], objc[r][t + 16*j]);

    fft256r<false,false>(v, fb, tw, t);  // row FFT of next fft2

    #pragma unroll
    for (int j = 0; j < 16; j++) p[t + 16*j] = v[j];
}

// ---------------------------------------------------------------------------
// k_zero: clear output (d_out poisoned by harness; k_final accumulates).
// ---------------------------------------------------------------------------
__global__ __launch_bounds__(256) void k_zero(float4* __restrict__ out)
{
    out[blockIdx.x * 256 + threadIdx.x] = make_float4(0.f, 0.f, 0.f, 0.f);
}

// ---------------------------------------------------------------------------
// k_final: col FFT + |.|^2, one probe mode per block, atomicAdd into out.
// grid (16, 32, 4) = (colgroup, batch, mode).
// ---------------------------------------------------------------------------
__global__ __launch_bounds__(256) void k_final(float* __restrict__ out)
{
    __shared__ float2 tw[16*17];
    __shared__ float2 buf[16*FSTRIDE];

    int tid = threadIdx.x;
    fill_tw(tw, tid);
    __syncthreads();

    int f = tid & 15, t = tid >> 4;
    int b = blockIdx.y;
    int m = blockIdx.z;
    int x = (blockIdx.x << 4) + f;
    float2* fb = buf + f*FSTRIDE;

    const float2* p = g_psi + (b*4 + m)*65536 + x;
    float2 v[16];
    #pragma unroll
    for (int j = 0; j < 16; j++) v[j] = p[(t + 16*j)*256];

    fft256r<false,true>(v, fb, tw, t, false);

    #pragma unroll
    for (int k1 = 0; k1 < 16; k1++){
        int kyy = 16*k1 + t;
        atomicAdd(out + b*65536 + kyy*256 + x,
                  v[k1].x*v[k1].x + v[k1].y*v[k1].y);
    }
}

// ---------------------------------------------------------------------------
extern "C" void kernel_launch(void* const* d_in, const int* in_sizes, int n_in,
                              void* d_out, int out_size)
{
    const float* obj     = (const float*)d_in[0];
    const float* probe   = (const float*)d_in[1];
    const float* shifts  = (const float*)d_in[2];
    const int*   crop    = (const int*)d_in[3];
    const float* Hr      = (const float*)d_in[4];
    const float* Hi      = (const float*)d_in[5];
    const int*   indices = (const int*)d_in[6];
    float* out = (float*)d_out;

    dim3 grow(64, BATCH);     // 4 rows x 4 modes per CTA
    dim3 gcol(16, NIMG);

    k_init<<<grow, 256>>>(obj, probe, shifts, crop, indices);
    for (int z = 1; z < NS; z++){
        k_col<<<gcol, 256>>>(Hr, Hi);
        k_row<<<grow, 256>>>(obj, crop, indices, z);
    }
    k_zero<<<(BATCH*N*N/4 + 255)/256, 256>>>((float4*)out);
    k_final<<<dim3(16, BATCH, PM), 256>>>(out);
}